// round 6
// baseline (speedup 1.0000x reference)
#include <cuda_runtime.h>

#define N_ANCH 5000
#define N_CLS 80
#define WORDS 157
#define WSTRIDE 160
#define W4 (WSTRIDE / 4)        // 40 uint4 per row
#define MAXB 300
#define SCORE_THR_F 0.05f
#define OUT_COLS 84
#define NBUCK 4096
#define KEYCAP 5120
#define CLS_T_STRIDE 5120
#define NTILES ((WORDS * (WORDS + 1)) / 2)
#define A_BLOCKS ((NTILES * 32 + 255) / 256)        // 1551
#define T_BLOCKS ((N_ANCH * N_CLS + 255) / 256)     // 1563
#define DEPTH 64
#define SCAN_T 256

__device__ unsigned int g_mask[N_ANCH * WSTRIDE];
__device__ unsigned int g_kept[N_CLS * WSTRIDE];
__device__ float        g_clsT[N_CLS * CLS_T_STRIDE];
__device__ unsigned int g_list[N_CLS * KEYCAP];
__device__ int          g_cnt[N_CLS];

// ---------------------------------------------------------------------------
// 32x32 warp bit transpose
// ---------------------------------------------------------------------------
__device__ __forceinline__ unsigned bit_transpose32(unsigned x, int lane) {
    const unsigned lom[5] = {0x0000FFFFu, 0x00FF00FFu, 0x0F0F0F0Fu, 0x33333333u, 0x55555555u};
    const int      shs[5] = {16, 8, 4, 2, 1};
#pragma unroll
    for (int s = 0; s < 5; ++s) {
        unsigned y = __shfl_xor_sync(0xffffffffu, x, shs[s]);
        unsigned lo = lom[s];
        if ((lane & shs[s]) == 0) x = (x & lo)  | ((y & lo)  << shs[s]);
        else                      x = (x & ~lo) | ((y & ~lo) >> shs[s]);
    }
    return x;
}

// ---------------------------------------------------------------------------
// Kernel P (fused): blocks [0, A_BLOCKS) do IoU tiles; rest transpose cls.
// ---------------------------------------------------------------------------
__global__ void __launch_bounds__(256)
prep_kernel(const float4* __restrict__ boxes, const float* __restrict__ cls) {
    __shared__ float4 sbox[8][32];
    __shared__ float  sarea[8][32];

    if (blockIdx.x >= A_BLOCKS) {
        int t = (blockIdx.x - A_BLOCKS) * 256 + threadIdx.x;
        if (t < N_ANCH * N_CLS) {
            int i = t / N_CLS, c = t - i * N_CLS;
            g_clsT[c * CLS_T_STRIDE + i] = cls[t];
        }
        return;
    }

    const int gw   = (blockIdx.x * blockDim.x + threadIdx.x) >> 5;
    const int lane = threadIdx.x & 31;
    const int wib  = (threadIdx.x >> 5);
    if (gw >= NTILES) return;

    int J = (int)((sqrtf(8.0f * (float)gw + 1.0f) - 1.0f) * 0.5f);
    while ((J + 1) * (J + 2) / 2 <= gw) ++J;
    while (J * (J + 1) / 2 > gw) --J;
    const int I = gw - J * (J + 1) / 2;

    const int row = (I << 5) + lane;
    const float4 bi = __ldg(&boxes[min(row, N_ANCH - 1)]);
    const float  ai = __fmul_rn(__fsub_rn(bi.z, bi.x), __fsub_rn(bi.w, bi.y));

    const int colL = (J << 5) + lane;
    {
        float4 bc = __ldg(&boxes[min(colL, N_ANCH - 1)]);
        sbox[wib][lane]  = bc;
        sarea[wib][lane] = __fmul_rn(__fsub_rn(bc.z, bc.x), __fsub_rn(bc.w, bc.y));
    }
    __syncwarp(0xffffffffu);

    unsigned word = 0u, fix = 0u;
#pragma unroll
    for (int j = 0; j < 32; ++j) {
        float4 bj = sbox[wib][j];
        float  aj = sarea[wib][j];
        float iw = fmaxf(__fsub_rn(fminf(bi.z, bj.z), fmaxf(bi.x, bj.x)), 0.0f);
        float ih = fmaxf(__fsub_rn(fminf(bi.w, bj.w), fmaxf(bi.y, bj.y)), 0.0f);
        float inter = __fmul_rn(iw, ih);
        float uni   = __fsub_rn(__fadd_rn(ai, aj), inter);
        float diff  = __fmaf_rn(inter, 2.0f, -uni);
        if (diff > 0.0f)                          word |= (1u << j);
        if (fabsf(diff) <= __fmul_rn(uni, 1e-6f)) fix  |= (1u << j);
    }

    if (__any_sync(0xffffffffu, fix != 0u)) {
        while (fix) {
            int j = __ffs(fix) - 1; fix &= fix - 1u;
            float4 bj = sbox[wib][j];
            float  aj = sarea[wib][j];
            float iw = fmaxf(__fsub_rn(fminf(bi.z, bj.z), fmaxf(bi.x, bj.x)), 0.0f);
            float ih = fmaxf(__fsub_rn(fminf(bi.w, bj.w), fmaxf(bi.y, bj.y)), 0.0f);
            float inter = __fmul_rn(iw, ih);
            float uni   = __fsub_rn(__fadd_rn(ai, aj), inter);
            float iou   = __fdiv_rn(inter, fmaxf(uni, 1e-8f));
            if (iou > 0.5f) word |=  (1u << j);
            else            word &= ~(1u << j);
        }
    }

    const unsigned cmaskJ = (J == WORDS - 1) ? 0xFFu : 0xFFFFFFFFu;
    const unsigned cmaskI = (I == WORDS - 1) ? 0xFFu : 0xFFFFFFFFu;
    word &= cmaskJ;

    if (I == J) {
        word &= ~(1u << lane);
        if (row < N_ANCH) g_mask[row * WSTRIDE + J] = word;
    } else {
        unsigned t = bit_transpose32(word, lane) & cmaskI;
        g_mask[row * WSTRIDE + J] = word;
        if (colL < N_ANCH) g_mask[colL * WSTRIDE + I] = t;
    }
}

// ---------------------------------------------------------------------------
// Kernel B1: per-class exact stable descending sort -> g_list / g_cnt
// ---------------------------------------------------------------------------
#define BT 1024

__global__ void __launch_bounds__(BT, 1)
sort_class_kernel() {
    extern __shared__ unsigned char sh_raw[];
    unsigned long long* keys = (unsigned long long*)sh_raw;
    unsigned int* hist   = (unsigned int*)(keys + KEYCAP);
    unsigned int* starts = hist + NBUCK;
    __shared__ unsigned int wsum[32];
    __shared__ int s_cnt;

    const int c = blockIdx.x;
    const int tid = threadIdx.x;
    const int lane = tid & 31;
    const int wid = tid >> 5;
    const float* col = &g_clsT[c * CLS_T_STRIDE];

    for (int b = tid; b < NBUCK; b += BT) hist[b] = 0u;
    __syncthreads();

    for (int i = tid; i < N_ANCH; i += BT) {
        float s = col[i];
        if (s > SCORE_THR_F) {
            int b = min((int)__fmul_rn(s, 4096.0f), NBUCK - 1);
            atomicAdd(&hist[NBUCK - 1 - b], 1u);
        }
    }
    __syncthreads();

    {
        unsigned h0 = hist[tid * 4 + 0], h1 = hist[tid * 4 + 1];
        unsigned h2 = hist[tid * 4 + 2], h3 = hist[tid * 4 + 3];
        unsigned tsum = h0 + h1 + h2 + h3;
        unsigned x = tsum;
#pragma unroll
        for (int o = 1; o < 32; o <<= 1) {
            unsigned y = __shfl_up_sync(0xffffffffu, x, o);
            if (lane >= o) x += y;
        }
        if (lane == 31) wsum[wid] = x;
        __syncthreads();
        if (wid == 0) {
            unsigned v = wsum[lane], xx = v;
#pragma unroll
            for (int o = 1; o < 32; o <<= 1) {
                unsigned y = __shfl_up_sync(0xffffffffu, xx, o);
                if (lane >= o) xx += y;
            }
            wsum[lane] = xx;
            if (lane == 31) s_cnt = (int)xx;
        }
        __syncthreads();
        unsigned te = ((wid > 0) ? wsum[wid - 1] : 0u) + (x - tsum);
        hist[tid * 4 + 0] = te;                  starts[tid * 4 + 0] = te;
        hist[tid * 4 + 1] = te + h0;             starts[tid * 4 + 1] = te + h0;
        hist[tid * 4 + 2] = te + h0 + h1;        starts[tid * 4 + 2] = te + h0 + h1;
        hist[tid * 4 + 3] = te + h0 + h1 + h2;   starts[tid * 4 + 3] = te + h0 + h1 + h2;
    }
    __syncthreads();
    const int cnt = s_cnt;

    for (int i = tid; i < N_ANCH; i += BT) {
        float s = col[i];
        if (s > SCORE_THR_F) {
            int b = min((int)__fmul_rn(s, 4096.0f), NBUCK - 1);
            unsigned pos = atomicAdd(&hist[NBUCK - 1 - b], 1u);
            keys[pos] = ((unsigned long long)__float_as_uint(s) << 32) |
                        (unsigned long long)(0xFFFFFFFFu - (unsigned)i);
        }
    }
    __syncthreads();

    for (int b = tid; b < NBUCK; b += BT) {
        int s0 = (int)starts[b], e0 = (int)hist[b];
        for (int i = s0 + 1; i < e0; ++i) {
            unsigned long long kv = keys[i];
            int j = i - 1;
            while (j >= s0 && keys[j] < kv) { keys[j + 1] = keys[j]; --j; }
            keys[j + 1] = kv;
        }
    }
    __syncthreads();

    if (tid == 0) g_cnt[c] = cnt;
    for (int p = tid; p < cnt; p += BT)
        g_list[c * KEYCAP + p] = 0xFFFFFFFFu - (unsigned)keys[p];
}

// ---------------------------------------------------------------------------
// Kernel B2: greedy scan, 256 threads/class, depth-64 batches, uint4 row loads
// ---------------------------------------------------------------------------
struct ScanShm {
    unsigned           slist[KEYCAP];        // 20480 B
    uint4              srow4[DEPTH][W4];     // 40960 B
    unsigned           supp[WSTRIDE];
    unsigned           keptb[WSTRIDE];
    unsigned long long sbits[DEPTH];
    unsigned long long s_kb;
    unsigned           s_m[8];
    unsigned           sanch[DEPTH];
    int                spsel[DEPTH];
    int                s_sel;
};

__global__ void __launch_bounds__(SCAN_T, 1)
nms_scan_kernel() {
    extern __shared__ unsigned char shraw[];
    ScanShm* S = (ScanShm*)shraw;
    const int c = blockIdx.x;
    const int tid = threadIdx.x;
    const int lane = tid & 31;
    const int w = tid >> 5;
    const int cnt = g_cnt[c];

    for (int i = tid; i < WSTRIDE; i += SCAN_T) { S->supp[i] = 0u; S->keptb[i] = 0u; }
    for (int i = tid; i < cnt; i += SCAN_T) S->slist[i] = __ldg(&g_list[c * KEYCAP + i]);
    __syncthreads();

    unsigned* srowW = (unsigned*)S->srow4;
    const uint4* gm4 = (const uint4*)g_mask;

    int count = 0;
    int cur = 0;
    while (cur < cnt && count < MAXB) {
        // 1) alive check over a 256-wide window
        int pos = cur + tid;
        bool ok = (pos < cnt);
        unsigned ca = ok ? S->slist[pos] : 0u;
        bool alive = ok && !((S->supp[ca >> 5] >> (ca & 31)) & 1u);
        unsigned bm = __ballot_sync(0xffffffffu, alive);
        if (lane == 0) S->s_m[w] = bm;
        __syncthreads();                                     // B1

        unsigned mw[8]; int tot = 0;
#pragma unroll
        for (int q = 0; q < 8; ++q) { mw[q] = S->s_m[q]; tot += __popc(mw[q]); }
        int nf = min(tot, DEPTH);
        if (nf == 0) { cur += SCAN_T; __syncthreads(); continue; }

        // 2) rank-select first nf alive (tid<DEPTH each finds its candidate)
        if (tid < DEPTH) {
            int rem = tid, psel = -1;
#pragma unroll
            for (int q = 0; q < 8; ++q) {
                int cq = __popc(mw[q]);
                if (psel < 0) {
                    if (rem < cq) psel = (q << 5) + (int)__fns(mw[q], 0, rem + 1);
                    else rem -= cq;
                }
            }
            if (tid < nf) {
                S->spsel[tid] = psel;
                S->sanch[tid] = S->slist[cur + psel];
            }
        }
        __syncthreads();                                     // B2

        // 3) row loads: 4 threads per row, 10 uint4 each
        {
            int k = tid >> 2, q = tid & 3;
            if (k < nf) {
                const uint4* src = &gm4[(size_t)S->sanch[k] * W4];
#pragma unroll
                for (int u = 0; u < 10; ++u)
                    S->srow4[k][q * 10 + u] = __ldg(&src[q * 10 + u]);
            }
        }
        __syncthreads();                                     // B3

        // 4) pairwise gather: candidate tid's 64-bit "suppressed-by" vector
        if (tid < nf) {
            unsigned aw = S->sanch[tid] >> 5, ab = S->sanch[tid] & 31u;
            unsigned lo = 0u, hi = 0u;
#pragma unroll
            for (int m = 0; m < 32; ++m)
                lo |= ((srowW[m * WSTRIDE + aw] >> ab) & 1u) << m;
#pragma unroll
            for (int m = 0; m < 32; ++m)
                hi |= ((srowW[(m + 32) * WSTRIDE + aw] >> ab) & 1u) << m;
            S->sbits[tid] = (unsigned long long)lo | ((unsigned long long)hi << 32);
        }
        __syncthreads();                                     // B4

        // 5) serial greedy resolve
        if (tid == 0) {
            unsigned long long kb = 0ull;
            int cl = count;
            for (int k = 0; k < nf && cl < MAXB; ++k)
                if (!(S->sbits[k] & kb)) { kb |= 1ull << k; ++cl; }
            S->s_kb = kb;
            S->s_sel = cl;
        }
        __syncthreads();                                     // B5

        unsigned long long kb = S->s_kb;
        count = S->s_sel;

        if (tid < nf && ((kb >> tid) & 1ull)) {
            unsigned a = S->sanch[tid];
            atomicOr(&S->keptb[a >> 5], 1u << (a & 31u));
        }
        // 6) supp OR: one thread per word, loop over selected rows (LDS only)
        if (tid < WSTRIDE) {
            unsigned acc = S->supp[tid];
            unsigned long long t = kb;
            while (t) {
                int k = __ffsll((long long)t) - 1; t &= t - 1ull;
                acc |= srowW[k * WSTRIDE + tid];
            }
            S->supp[tid] = acc;
        }
        __syncthreads();                                     // B6

        cur += S->spsel[nf - 1] + 1;
    }
    __syncthreads();

    for (int i = tid; i < WSTRIDE; i += SCAN_T)
        g_kept[c * WSTRIDE + i] = S->keptb[i];
}

// ---------------------------------------------------------------------------
// Kernel C: assemble output (1,5000,84)
// ---------------------------------------------------------------------------
__global__ void assemble_kernel(const float* __restrict__ boxes,
                                const float* __restrict__ cls,
                                float* __restrict__ out) {
    int t = blockIdx.x * blockDim.x + threadIdx.x;
    if (t >= N_ANCH * OUT_COLS) return;
    int i = t / OUT_COLS;
    int col = t - i * OUT_COLS;
    float v;
    if (col < 4) {
        v = boxes[i * 4 + col];
    } else {
        int cc = col - 4;
        float s = cls[i * N_CLS + cc];
        unsigned m = g_kept[cc * WSTRIDE + (i >> 5)];
        v = ((m >> (i & 31)) & 1u) ? s : 0.0f;
    }
    out[t] = v;
}

// ---------------------------------------------------------------------------
extern "C" void kernel_launch(void* const* d_in, const int* in_sizes, int n_in,
                              void* d_out, int out_size) {
    const float* boxes = (const float*)d_in[0];
    const float* cls   = (const float*)d_in[1];
    float* out = (float*)d_out;

    {   // P: fused IoU tiles + transpose
        prep_kernel<<<A_BLOCKS + T_BLOCKS, 256>>>((const float4*)boxes, cls);
    }
    {   // B1: per-class sort
        size_t smem = (size_t)KEYCAP * 8 + (size_t)NBUCK * 4 * 2;
        cudaFuncSetAttribute(sort_class_kernel,
                             cudaFuncAttributeMaxDynamicSharedMemorySize,
                             (int)smem);
        sort_class_kernel<<<N_CLS, BT, smem>>>();
    }
    {   // B2: greedy scan
        size_t smem = sizeof(ScanShm);
        cudaFuncSetAttribute(nms_scan_kernel,
                             cudaFuncAttributeMaxDynamicSharedMemorySize,
                             (int)smem);
        nms_scan_kernel<<<N_CLS, SCAN_T, smem>>>();
    }
    {   // C: assemble
        int total = N_ANCH * OUT_COLS;
        assemble_kernel<<<(total + 255) / 256, 256>>>(boxes, cls, out);
    }
}